// round 15
// baseline (speedup 1.0000x reference)
#include <cuda_runtime.h>

// LIF recurrence, forward spikes only.
// x: [T=32, B, D] fp32, out: same shape, spikes in {0.0, 1.0}.
//   mem_t = dec_{t-1} + x_t ; spike_t = mem_t > 0.5
//   dec_t = spike_t ? 0 : mem_t * 0.25        (dec_{-1} = 0)
//
// Converged structure (R4/R14): depth-8 ping-pong register pipeline, in-place
// compute, burst stores. R15 tweak: 128-thread CTAs. At regs~94, a 256-thr
// CTA books 24064 regs -> only 2 CTAs/SM (27% of the RF stranded). 128-thr
// CTAs book 12032 -> 5 CTAs/SM = 20 warps (+25%), and grid 2048 halves the
// last-wave tail waste.

#define THRESH 0.5f
#define DECAY  0.25f

__device__ __forceinline__ void load8(float4 (&b)[8], const float4* __restrict__ p,
                                      long st)
{
    #pragma unroll
    for (int k = 0; k < 8; k++)
        b[k] = __ldcs(p + (long)k * st);
}

// Compute 8 timesteps; spikes overwrite the load buffer in place.
__device__ __forceinline__ void compute8(float4 (&b)[8], float4& dec)
{
    #pragma unroll
    for (int k = 0; k < 8; k++) {
        float mx = dec.x + b[k].x;
        float my = dec.y + b[k].y;
        float mz = dec.z + b[k].z;
        float mw = dec.w + b[k].w;

        b[k].x = (mx > THRESH) ? 1.0f : 0.0f;
        b[k].y = (my > THRESH) ? 1.0f : 0.0f;
        b[k].z = (mz > THRESH) ? 1.0f : 0.0f;
        b[k].w = (mw > THRESH) ? 1.0f : 0.0f;

        dec.x = (mx > THRESH) ? 0.0f : mx * DECAY;
        dec.y = (my > THRESH) ? 0.0f : my * DECAY;
        dec.z = (mz > THRESH) ? 0.0f : mz * DECAY;
        dec.w = (mw > THRESH) ? 0.0f : mw * DECAY;
    }
}

__device__ __forceinline__ void store8(const float4 (&b)[8],
                                       float4* __restrict__ op, long st)
{
    #pragma unroll
    for (int k = 0; k < 8; k++)
        __stcs(op + (long)k * st, b[k]);
}

__global__ __launch_bounds__(128) void lif_kernel(
    const float4* __restrict__ x,
    float4* __restrict__ out,
    int chains4)   // BD / 4
{
    int i = blockIdx.x * blockDim.x + threadIdx.x;
    const long st = chains4;
    const float4* __restrict__ xp = x + i;
    float4* __restrict__       op = out + i;

    float4 A[8], B[8];
    float4 dec = make_float4(0.0f, 0.0f, 0.0f, 0.0f);

    load8(A, xp, st);                    // t 0..7   in flight
    load8(B, xp + 8 * st, st);           // t 8..15  in flight

    compute8(A, dec);
    store8(A, op, st);
    load8(A, xp + 16 * st, st);          // t 16..23 in flight

    compute8(B, dec);
    store8(B, op + 8 * st, st);
    load8(B, xp + 24 * st, st);          // t 24..31 in flight

    compute8(A, dec);
    store8(A, op + 16 * st, st);

    compute8(B, dec);
    store8(B, op + 24 * st, st);
}

extern "C" void kernel_launch(void* const* d_in, const int* in_sizes, int n_in,
                              void* d_out, int out_size)
{
    const float* x = (const float*)d_in[0];
    float* out = (float*)d_out;

    const int T = 32;
    int total = in_sizes[0];        // T * B * D
    int BD = total / T;             // 1,048,576
    int chains4 = BD / 4;           // 262,144

    int threads = 128;
    int blocks = chains4 / threads; // exact: 2048
    lif_kernel<<<blocks, threads>>>((const float4*)x, (float4*)out, chains4);
}

// round 16
// speedup vs baseline: 1.0014x; 1.0014x over previous
#include <cuda_runtime.h>

// LIF recurrence, forward spikes only.  [FINAL — converged at the HBM roofline]
// x: [T=32, B, D] fp32, out: same shape, spikes in {0.0, 1.0}.
//   mem_t = dec_{t-1} + x_t ; spike_t = mem_t > 0.5
//   dec_t = spike_t ? 0 : mem_t * 0.25        (dec_{-1} = 0)
//
// Convergence evidence (R2-R15): serial unroll 4/8/16, reg pipelines depth
// 4/8, 256-bit ld/st, TMA smem rings, phase-separated bulk I/O, L2 pinning
// (full/partial/evict_last/WT), persistent grids, wave geometry, CTA sizes
// 128/256 -> ALL land at 36.7 +/- 0.6 us ncu, DRAM 73-74% of 8 TB/s spec.
// ~74% is this part's mixed R+W ceiling for a 256 MB touch-once stream; the
// kernel is memory-roofline-bound at entitlement.
//
// Winning structure: depth-8 double-buffered register pipeline (loads of the
// next 8 timesteps always in flight behind compute), compute-in-place over
// the load buffer (zero extra registers), 8 back-to-back STG.128 per chunk
// (4 KB same-direction warp bursts), streaming .cs on both directions
// (touch-once data, no L2 value).

#define THRESH 0.5f
#define DECAY  0.25f

__device__ __forceinline__ void load8(float4 (&b)[8], const float4* __restrict__ p,
                                      long st)
{
    #pragma unroll
    for (int k = 0; k < 8; k++)
        b[k] = __ldcs(p + (long)k * st);
}

// Compute 8 timesteps; spikes overwrite the load buffer in place.
__device__ __forceinline__ void compute8(float4 (&b)[8], float4& dec)
{
    #pragma unroll
    for (int k = 0; k < 8; k++) {
        float mx = dec.x + b[k].x;
        float my = dec.y + b[k].y;
        float mz = dec.z + b[k].z;
        float mw = dec.w + b[k].w;

        b[k].x = (mx > THRESH) ? 1.0f : 0.0f;
        b[k].y = (my > THRESH) ? 1.0f : 0.0f;
        b[k].z = (mz > THRESH) ? 1.0f : 0.0f;
        b[k].w = (mw > THRESH) ? 1.0f : 0.0f;

        dec.x = (mx > THRESH) ? 0.0f : mx * DECAY;
        dec.y = (my > THRESH) ? 0.0f : my * DECAY;
        dec.z = (mz > THRESH) ? 0.0f : mz * DECAY;
        dec.w = (mw > THRESH) ? 0.0f : mw * DECAY;
    }
}

// 8 back-to-back streaming stores: one 4 KB same-direction warp burst.
__device__ __forceinline__ void store8(const float4 (&b)[8],
                                       float4* __restrict__ op, long st)
{
    #pragma unroll
    for (int k = 0; k < 8; k++)
        __stcs(op + (long)k * st, b[k]);
}

__global__ __launch_bounds__(256) void lif_kernel(
    const float4* __restrict__ x,
    float4* __restrict__ out,
    int chains4)   // BD / 4
{
    int i = blockIdx.x * blockDim.x + threadIdx.x;
    const long st = chains4;
    const float4* __restrict__ xp = x + i;
    float4* __restrict__       op = out + i;

    float4 A[8], B[8];
    float4 dec = make_float4(0.0f, 0.0f, 0.0f, 0.0f);

    load8(A, xp, st);                    // t 0..7   in flight
    load8(B, xp + 8 * st, st);           // t 8..15  in flight

    compute8(A, dec);
    store8(A, op, st);
    load8(A, xp + 16 * st, st);          // t 16..23 in flight

    compute8(B, dec);
    store8(B, op + 8 * st, st);
    load8(B, xp + 24 * st, st);          // t 24..31 in flight

    compute8(A, dec);
    store8(A, op + 16 * st, st);

    compute8(B, dec);
    store8(B, op + 24 * st, st);
}

extern "C" void kernel_launch(void* const* d_in, const int* in_sizes, int n_in,
                              void* d_out, int out_size)
{
    const float* x = (const float*)d_in[0];
    float* out = (float*)d_out;

    const int T = 32;
    int total = in_sizes[0];        // T * B * D
    int BD = total / T;             // 1,048,576
    int chains4 = BD / 4;           // 262,144

    int threads = 256;
    int blocks = chains4 / threads; // exact: 1024
    lif_kernel<<<blocks, threads>>>((const float4*)x, (float4*)out, chains4);
}

// round 17
// speedup vs baseline: 1.0021x; 1.0007x over previous
#include <cuda_runtime.h>

// LIF recurrence, forward spikes only.  [FINAL — converged at the HBM roofline]
// x: [T=32, B, D] fp32, out: same shape, spikes in {0.0, 1.0}.
//   mem_t = dec_{t-1} + x_t ; spike_t = mem_t > 0.5
//   dec_t = spike_t ? 0 : mem_t * 0.25        (dec_{-1} = 0)
//
// Convergence evidence (R2-R16): serial unroll 4/8/16, reg pipelines depth
// 4/8, 256-bit ld/st, TMA smem rings, phase-separated bulk I/O, L2 pinning
// (full/partial/evict_last/WT), persistent grids, wave geometry, CTA sizes
// 128/256 -> ALL land at 36.7-38.0 us ncu (run-to-run noise ±0.7 us),
// DRAM 72-74% of 8 TB/s spec. ~74% is this part's mixed R+W ceiling for a
// 256 MB touch-once stream; the kernel is memory-roofline-bound at
// entitlement. R16 reproduced R14's wall (45.216 us) exactly.
//
// Winning structure: depth-8 double-buffered register pipeline (loads of the
// next 8 timesteps always in flight behind compute), compute-in-place over
// the load buffer (zero extra registers), 8 back-to-back STG.128 per chunk
// (4 KB same-direction warp bursts), streaming .cs on both directions
// (touch-once data, no L2 value).

#define THRESH 0.5f
#define DECAY  0.25f

__device__ __forceinline__ void load8(float4 (&b)[8], const float4* __restrict__ p,
                                      long st)
{
    #pragma unroll
    for (int k = 0; k < 8; k++)
        b[k] = __ldcs(p + (long)k * st);
}

// Compute 8 timesteps; spikes overwrite the load buffer in place.
__device__ __forceinline__ void compute8(float4 (&b)[8], float4& dec)
{
    #pragma unroll
    for (int k = 0; k < 8; k++) {
        float mx = dec.x + b[k].x;
        float my = dec.y + b[k].y;
        float mz = dec.z + b[k].z;
        float mw = dec.w + b[k].w;

        b[k].x = (mx > THRESH) ? 1.0f : 0.0f;
        b[k].y = (my > THRESH) ? 1.0f : 0.0f;
        b[k].z = (mz > THRESH) ? 1.0f : 0.0f;
        b[k].w = (mw > THRESH) ? 1.0f : 0.0f;

        dec.x = (mx > THRESH) ? 0.0f : mx * DECAY;
        dec.y = (my > THRESH) ? 0.0f : my * DECAY;
        dec.z = (mz > THRESH) ? 0.0f : mz * DECAY;
        dec.w = (mw > THRESH) ? 0.0f : mw * DECAY;
    }
}

// 8 back-to-back streaming stores: one 4 KB same-direction warp burst.
__device__ __forceinline__ void store8(const float4 (&b)[8],
                                       float4* __restrict__ op, long st)
{
    #pragma unroll
    for (int k = 0; k < 8; k++)
        __stcs(op + (long)k * st, b[k]);
}

__global__ __launch_bounds__(256) void lif_kernel(
    const float4* __restrict__ x,
    float4* __restrict__ out,
    int chains4)   // BD / 4
{
    int i = blockIdx.x * blockDim.x + threadIdx.x;
    const long st = chains4;
    const float4* __restrict__ xp = x + i;
    float4* __restrict__       op = out + i;

    float4 A[8], B[8];
    float4 dec = make_float4(0.0f, 0.0f, 0.0f, 0.0f);

    load8(A, xp, st);                    // t 0..7   in flight
    load8(B, xp + 8 * st, st);           // t 8..15  in flight

    compute8(A, dec);
    store8(A, op, st);
    load8(A, xp + 16 * st, st);          // t 16..23 in flight

    compute8(B, dec);
    store8(B, op + 8 * st, st);
    load8(B, xp + 24 * st, st);          // t 24..31 in flight

    compute8(A, dec);
    store8(A, op + 16 * st, st);

    compute8(B, dec);
    store8(B, op + 24 * st, st);
}

extern "C" void kernel_launch(void* const* d_in, const int* in_sizes, int n_in,
                              void* d_out, int out_size)
{
    const float* x = (const float*)d_in[0];
    float* out = (float*)d_out;

    const int T = 32;
    int total = in_sizes[0];        // T * B * D
    int BD = total / T;             // 1,048,576
    int chains4 = BD / 4;           // 262,144

    int threads = 256;
    int blocks = chains4 / threads; // exact: 1024
    lif_kernel<<<blocks, threads>>>((const float4*)x, (float4*)out, chains4);
}